// round 15
// baseline (speedup 1.0000x reference)
#include <cuda_runtime.h>
#include <cuda_fp16.h>
#include <cstdint>
#include <cstddef>

// out[256,11008] = x[256,4096] @ W[11008,4096]^T * scale + bias, W ternary i32.
// fp16 mma.sync m16n8k16 single pass, fp32 accum (rel_err ~2e-4 << 1e-3).
// WARP-SPECIALIZED, DEEP-PIPELINED PRODUCER (this round's change):
//   RING=4 stages. Producer at iter k: cpA(k) issue, STS W(k) from regs
//   loaded at k-2, wait_group 1 (guarantees only A(k-1)), arrive FULL(k-1).
//   -> no DRAM latency on the per-iter critical path (1 full iter of slack
//   for A, 2 iters for W). 8 consumer warps (2n x 4m, 64x40) unchanged.
// BM=256 (full M). Mixed BN: 96 x 80 + 52 x 64 = 11008 -> 148 CTAs, one wave.

#define M_TOK   256
#define K_DIM   4096
#define N_DIM   11008
#define BK      64
#define KITERS  (K_DIM / BK)          // 64
#define THREADS 384                   // 8 consumer + 4 producer warps
#define GRID    148
#define RING    4

#define ROWB    144
#define A_BYTES (256 * ROWB)          // 36864
#define B_BYTES (80 * ROWB)           // 11520 (max BN)
#define STG     (A_BYTES + B_BYTES)   // 48384
#define SMEM_ALLOC (RING * STG)       // 193536 (<= 227KB)

// named barrier ids: 1..4 = full[s], 5..8 = free[s]
#define FULL0 1
#define FREE0 5

__device__ __half g_xh[M_TOK * K_DIM];

// ---------------- asm helpers ----------------
__device__ __forceinline__ uint32_t smem_u32(const void* p) {
    uint32_t a;
    asm("{ .reg .u64 t; cvta.to.shared.u64 t, %1; cvt.u32.u64 %0, t; }"
        : "=r"(a) : "l"(p));
    return a;
}
__device__ __forceinline__ void bar_sync_named(int id) {
    asm volatile("bar.sync %0, 384;" :: "r"(id) : "memory");
}
__device__ __forceinline__ void bar_arrive_named(int id) {
    asm volatile("bar.arrive %0, 384;" :: "r"(id) : "memory");
}
__device__ __forceinline__ void cp16(uint32_t dst, const void* src) {
    asm volatile("cp.async.cg.shared.global [%0], [%1], 16;"
        :: "r"(dst), "l"(src) : "memory");
}
#define CP_COMMIT() asm volatile("cp.async.commit_group;" ::: "memory")
#define CP_WAIT1()  asm volatile("cp.async.wait_group 1;" ::: "memory")
#define CP_WAIT0()  asm volatile("cp.async.wait_group 0;" ::: "memory")

__device__ __forceinline__ void ldsm4(uint32_t* r, uint32_t addr) {
    asm volatile("ldmatrix.sync.aligned.m8n8.x4.shared.b16 {%0,%1,%2,%3}, [%4];"
        : "=r"(r[0]), "=r"(r[1]), "=r"(r[2]), "=r"(r[3]) : "r"(addr));
}
__device__ __forceinline__ void ldsm2(uint32_t* r, uint32_t addr) {
    asm volatile("ldmatrix.sync.aligned.m8n8.x2.shared.b16 {%0,%1}, [%2];"
        : "=r"(r[0]), "=r"(r[1]) : "r"(addr));
}
__device__ __forceinline__ void mma_f16(float* c, const uint32_t* a,
                                        const uint32_t* b) {
    asm volatile(
        "mma.sync.aligned.m16n8k16.row.col.f32.f16.f16.f32 "
        "{%0,%1,%2,%3}, {%4,%5,%6,%7}, {%8,%9}, {%0,%1,%2,%3};"
        : "+f"(c[0]), "+f"(c[1]), "+f"(c[2]), "+f"(c[3])
        : "r"(a[0]), "r"(a[1]), "r"(a[2]), "r"(a[3]), "r"(b[0]), "r"(b[1]));
}
__device__ __forceinline__ uint32_t w2h2(uint32_t w0, uint32_t w1) {
    uint32_t c = __byte_perm(w0, w1, 0x5410);
    return ((c & 0x00010001u) * 0x3C00u) | (c & 0x80008000u);
}

// ---------------- x convert pre-kernel ----------------
__global__ void conv_x_kernel(const float* __restrict__ x) {
    int i = (blockIdx.x * blockDim.x + threadIdx.x) << 2;
    float4 v = *reinterpret_cast<const float4*>(x + i);
    __half2* ph = reinterpret_cast<__half2*>(g_xh + i);
    ph[0] = __floats2half2_rn(v.x, v.y);
    ph[1] = __floats2half2_rn(v.z, v.w);
}

// ---------------- main GEMM ----------------
__global__ void __launch_bounds__(THREADS, 1)
bitnet_gemm_kernel(const int* __restrict__ qw, const float* __restrict__ scale,
                   const float* __restrict__ bias, float* __restrict__ out) {
    extern __shared__ char smem[];
    const uint32_t su = smem_u32(smem);

    const int tid = threadIdx.x, wid = tid >> 5, lane = tid & 31;
    const int cta = blockIdx.x;
    int n0, n_sz;
    if (cta < 96) { n0 = cta * 80; n_sz = 80; }
    else          { n0 = 7680 + (cta - 96) * 64; n_sz = 64; }

    if (wid >= 8) {
        // ================= PRODUCER (warps 8-11, 128 threads) =================
        const int ptid = tid - 256;
        const int w_kp = ptid & 7, w_row0 = ptid >> 3;
        const int nWr = n_sz >> 4;                 // 5 (BN=80) or 4 (BN=64)
        const int* wbase = qw + (size_t)n0 * K_DIM + w_kp * 8;
        int woff[5];
#pragma unroll
        for (int j = 0; j < 5; ++j) woff[j] = (w_row0 + 16 * j) * K_DIM;
        const int a_kc = ptid & 7, a_row0 = ptid >> 3;
        const __half* abase = g_xh + (size_t)a_row0 * K_DIM + a_kc * 8;
        const uint32_t ad0 = (uint32_t)(a_row0 * ROWB + a_kc * 16);

        uint32_t wreg[2][40];                      // 2-iter slack for W LDGs
        auto ldgW = [&](int k0, int buf) {
#pragma unroll
            for (int j = 0; j < 5; ++j) {
                if (j < nWr) {
                    const int* s = wbase + woff[j] + k0;
                    asm volatile("ld.global.cs.v4.u32 {%0,%1,%2,%3}, [%4];"
                        : "=r"(wreg[buf][8*j]),   "=r"(wreg[buf][8*j+1]),
                          "=r"(wreg[buf][8*j+2]), "=r"(wreg[buf][8*j+3]) : "l"(s));
                    asm volatile("ld.global.cs.v4.u32 {%0,%1,%2,%3}, [%4];"
                        : "=r"(wreg[buf][8*j+4]), "=r"(wreg[buf][8*j+5]),
                          "=r"(wreg[buf][8*j+6]), "=r"(wreg[buf][8*j+7]) : "l"(s + 4));
                }
            }
        };

        ldgW(0, 0);                                // W(0)
        ldgW(BK, 1);                               // W(1)
#pragma unroll 1
        for (int k = 0; k < KITERS; ++k) {
            const int s = k % RING;
            if (k >= RING) bar_sync_named(FREE0 + s);   // stage free
            const uint32_t st = su + (uint32_t)(s * STG);
            // issue A(k) (do NOT wait for it this iteration)
#pragma unroll
            for (int j = 0; j < 16; ++j)
                cp16(st + ad0 + (uint32_t)(j * 16 * ROWB),
                     abase + (size_t)j * 16 * K_DIM + k * BK);
            CP_COMMIT();
            // STS W(k) from regs loaded at iter k-2
            const uint32_t stB = st + A_BYTES;
            const int wb = k & 1;
#pragma unroll
            for (int j = 0; j < 5; ++j) {
                if (j < nWr) {
                    uint32_t p0 = w2h2(wreg[wb][8*j],   wreg[wb][8*j+1]);
                    uint32_t p1 = w2h2(wreg[wb][8*j+2], wreg[wb][8*j+3]);
                    uint32_t p2 = w2h2(wreg[wb][8*j+4], wreg[wb][8*j+5]);
                    uint32_t p3 = w2h2(wreg[wb][8*j+6], wreg[wb][8*j+7]);
                    asm volatile("st.shared.v4.b32 [%0], {%1,%2,%3,%4};"
                        :: "r"(stB + (uint32_t)((w_row0 + 16*j) * ROWB + w_kp * 16)),
                           "r"(p0), "r"(p1), "r"(p2), "r"(p3) : "memory");
                }
            }
            if (k + 2 < KITERS) ldgW((k + 2) * BK, wb);  // W(k+2), 2-iter slack
            if (k >= 1) {
                CP_WAIT1();                        // guarantees A(k-1) landed
                __threadfence_block();
                bar_arrive_named(FULL0 + ((k - 1) % RING));   // publish k-1
            }
        }
        // epilogue: publish the last stage
        CP_WAIT0();
        __threadfence_block();
        bar_arrive_named(FULL0 + ((KITERS - 1) % RING));
    } else {
        // ================= CONSUMER (warps 0-7, 256 threads) =================
        const int warp_m = wid & 3;        // 4 m-groups, 64 rows each
        const int warp_n = wid >> 2;       // 2 n-groups, 40 cols each
        const int nbase = warp_n * 40;
        int ntiles = (n_sz - nbase) >> 3;
        if (ntiles > 5) ntiles = 5;
        if (ntiles < 0) ntiles = 0;
        const bool full = (ntiles == 5);

        const uint32_t a_off = (uint32_t)((warp_m * 64 + (lane & 15)) * ROWB +
                                          ((lane >> 4) << 4));
        const uint32_t b_off4 = (uint32_t)((nbase + ((lane >> 4) << 3) + (lane & 7)) * ROWB +
                                           (((lane >> 3) & 1) << 4));
        const uint32_t b_off2 = (uint32_t)((nbase + 32 + (lane & 7)) * ROWB +
                                           (((lane >> 3) & 1) << 4));
        const uint32_t b_offs = (uint32_t)((nbase + (lane & 7)) * ROWB +
                                           (((lane >> 3) & 1) << 4));

        float acc[4][5][4];
#pragma unroll
        for (int mt = 0; mt < 4; ++mt)
#pragma unroll
            for (int nt = 0; nt < 5; ++nt)
#pragma unroll
                for (int r = 0; r < 4; ++r) acc[mt][nt][r] = 0.0f;

        uint32_t af[2][4][4], bf[2][5][2];

        auto load_frags = [&](uint32_t stA, uint32_t stB, int ks, int buf) {
            const uint32_t ksb = (uint32_t)(ks * 32);
            if (full) {
                ldsm4(&bf[buf][0][0], stB + b_off4 + ksb);
                ldsm4(&bf[buf][2][0], stB + b_off4 + 16 * ROWB + ksb);
                ldsm2(&bf[buf][4][0], stB + b_off2 + ksb);
            } else {
#pragma unroll
                for (int nt = 0; nt < 5; ++nt)
                    if (nt < ntiles)
                        ldsm2(&bf[buf][nt][0],
                              stB + b_offs + (uint32_t)(nt * 8 * ROWB) + ksb);
            }
#pragma unroll
            for (int mt = 0; mt < 4; ++mt)
                ldsm4(af[buf][mt], stA + a_off + (uint32_t)(mt * 16 * ROWB) + ksb);
        };

        // prime: wait stage 0 full, load its first frags
        bar_sync_named(FULL0 + 0);
        load_frags(su, su + A_BYTES, 0, 0);

#pragma unroll 1
        for (int k = 0; k < KITERS; ++k) {
            const int s = k % RING;
            const uint32_t stA = su + (uint32_t)(s * STG);
            const uint32_t stB = stA + A_BYTES;
#pragma unroll
            for (int ks = 0; ks < 4; ++ks) {
                const int buf = ks & 1;
                if (ks < 3) {
                    load_frags(stA, stB, ks + 1, buf ^ 1);
                } else if (k + 1 < KITERS) {
                    const int s2 = (k + 1) % RING;
                    bar_sync_named(FULL0 + s2);         // usually already passed
                    const uint32_t nA = su + (uint32_t)(s2 * STG);
                    load_frags(nA, nA + A_BYTES, 0, buf ^ 1);
                }
#pragma unroll
                for (int mt = 0; mt < 4; ++mt)
#pragma unroll
                    for (int nt = 0; nt < 5; ++nt)
                        if (nt < ntiles)
                            mma_f16(acc[mt][nt], af[buf][mt], bf[buf][nt]);
            }
            if (k < KITERS - RING) bar_arrive_named(FREE0 + s);
        }

        // ---- epilogue: scale/bias + store ----
        const int row_base = warp_m * 64 + (lane >> 2);
        const int col_base = n0 + nbase + ((lane & 3) << 1);
#pragma unroll
        for (int mt = 0; mt < 4; ++mt) {
#pragma unroll
            for (int nt = 0; nt < 5; ++nt) {
                if (nt < ntiles) {
                    int col = col_base + nt * 8;
                    float2 sc = *reinterpret_cast<const float2*>(scale + col);
                    float2 bs = *reinterpret_cast<const float2*>(bias + col);
                    int r0 = row_base + mt * 16;
                    float2 o0, o1;
                    o0.x = acc[mt][nt][0] * sc.x + bs.x;
                    o0.y = acc[mt][nt][1] * sc.y + bs.y;
                    o1.x = acc[mt][nt][2] * sc.x + bs.x;
                    o1.y = acc[mt][nt][3] * sc.y + bs.y;
                    *reinterpret_cast<float2*>(out + (size_t)r0 * N_DIM + col) = o0;
                    *reinterpret_cast<float2*>(out + (size_t)(r0 + 8) * N_DIM + col) = o1;
                }
            }
        }
    }
}

// ---------------- launch ----------------
extern "C" void kernel_launch(void* const* d_in, const int* in_sizes, int n_in,
                              void* d_out, int out_size) {
    const float* x = nullptr; const int* qw = nullptr;
    const float* scale = nullptr; const float* bias = nullptr;
    for (int i = 0; i < n_in; ++i) {
        if (in_sizes[i] == M_TOK * K_DIM) x = (const float*)d_in[i];
        else if (in_sizes[i] == N_DIM * K_DIM) qw = (const int*)d_in[i];
        else if (in_sizes[i] == N_DIM) {
            if (!scale) scale = (const float*)d_in[i];
            else bias = (const float*)d_in[i];
        }
    }
    float* out = (float*)d_out;

    cudaFuncSetAttribute(bitnet_gemm_kernel,
                         cudaFuncAttributeMaxDynamicSharedMemorySize, SMEM_ALLOC);

    conv_x_kernel<<<(M_TOK * K_DIM) / (256 * 4), 256>>>(x);
    bitnet_gemm_kernel<<<GRID, THREADS, SMEM_ALLOC>>>(qw, scale, bias, out);
}